// round 16
// baseline (speedup 1.0000x reference)
#include <cuda_runtime.h>
#include <cuda_fp16.h>
#include <cstdint>

#define TKN 8192   // tokens = 4*2048
#define NF  4096   // in features
#define OF  4096   // out features

// Scratch (static device globals -- allocation-free per harness rules)
__device__ __half g_x[(size_t)TKN * NF];    // 64 MB: x*SU*Wscale, fp16
__device__ __half g_w[(size_t)OF * NF];     // 32 MB: W'' = H_o*W*H_i / 4096
__device__ __half g_tmp[(size_t)OF * NF];   // 32 MB: W-FWHT intermediate

// ---------------------------------------------------------------------------
// Kernel 1: g_x = fp16( input * SU * Wscale )   (pure streaming — both FWHTs
// now live on the W side: (X H) W^T = X (W H)^T, H symmetric)
// ---------------------------------------------------------------------------
__global__ __launch_bounds__(256) void scale_kernel(
        const float* __restrict__ in, const float* __restrict__ SU,
        const float* __restrict__ wscale) {
    const int row = blockIdx.x;
    const int tid = threadIdx.x;
    const float ws = wscale[0];

    const float4* ip = (const float4*)(in + (size_t)row * NF + tid * 16);
    const float4* up = (const float4*)(SU + tid * 16);
    __align__(16) __half2 h[8];
    #pragma unroll
    for (int q = 0; q < 4; q++) {
        float4 a = ip[q], b = up[q];
        h[q*2+0] = __floats2half2_rn(a.x * b.x * ws, a.y * b.y * ws);
        h[q*2+1] = __floats2half2_rn(a.z * b.z * ws, a.w * b.w * ws);
    }
    uint4* d = (uint4*)(g_x + (size_t)row * NF + tid * 16);
    d[0] = *(const uint4*)&h[0];
    d[1] = *(const uint4*)&h[4];
}

// ---------------------------------------------------------------------------
// Kernel 2: fused dequant + FWHT pass over output-dim bits 0..5 (R14 config).
// 128 threads/block, ONE half-lane per thread (occupancy-optimized, R12 win).
// ---------------------------------------------------------------------------
__global__ __launch_bounds__(128) void wfwht0_kernel(
        const float* __restrict__ cb, const int* __restrict__ qidx) {
    __shared__ float scb[1024];               // cb: 256 codes x 4 floats = 4KB
    const int tid = threadIdx.x;
    ((float4*)scb)[tid]       = ((const float4*)cb)[tid];
    ((float4*)scb)[tid + 128] = ((const float4*)cb)[tid + 128];
    __syncthreads();

    const int b  = blockIdx.x;                // 0..63
    const int hc = blockIdx.y * 128 + tid;    // half-col (= input index i)
    const int qcol = hc >> 2;
    const int sub  = hc & 3;
    const int* qrow = qidx + (size_t)b * 64 * (NF / 4) + qcol;

    float v[64];
    #pragma unroll
    for (int r = 0; r < 64; r++) {
        int q = __ldg(qrow + (size_t)r * (NF / 4));
        v[r] = scb[q * 4 + sub];
    }

    #pragma unroll
    for (int h = 1; h < 64; h <<= 1)
        #pragma unroll
        for (int i = 0; i < 64; i++)
            if (!(i & h)) {
                float a = v[i], c = v[i ^ h];
                v[i] = a + c; v[i ^ h] = a - c;
            }

    __half* d = g_tmp + (size_t)b * 64 * NF + hc;
    #pragma unroll
    for (int r = 0; r < 64; r++)
        d[(size_t)r * NF] = __float2half_rn(v[r]);
}

// ---------------------------------------------------------------------------
// Kernel 2b: FWHT pass over output-dim bits 6..11 (rows o = b + 64*r).
// ---------------------------------------------------------------------------
__global__ __launch_bounds__(128) void wfwht1_kernel() {
    const int b  = blockIdx.x;                // 0..63
    const int hc = blockIdx.y * 128 + threadIdx.x;
    const __half* s = g_tmp + (size_t)b * NF + hc;
    __half*       d = g_w   + (size_t)b * NF + hc;
    const size_t rstep = (size_t)64 * NF;

    float v[64];
    #pragma unroll
    for (int r = 0; r < 64; r++)
        v[r] = __half2float(__ldg(s + r * rstep));

    #pragma unroll
    for (int h = 1; h < 64; h <<= 1)
        #pragma unroll
        for (int i = 0; i < 64; i++)
            if (!(i & h)) {
                float a = v[i], c = v[i ^ h];
                v[i] = a + c; v[i ^ h] = a - c;
            }

    #pragma unroll
    for (int r = 0; r < 64; r++)
        d[r * rstep] = __float2half_rn(v[r]);
}

// ---------------------------------------------------------------------------
// Kernel 2c: in-place FWHT of W along the INPUT dim (one o-row per block,
// rows are i-contiguous). Shuffle-free 3-view core (R14-verified):
//   view1: i = tid*16 + j, view2: i = hi*256 + j*16 + lo, view3: i = j*256+tid
// Final write folds the exact power-of-two scale 1/4096 (= 1/64 * 1/64 from
// both FWHT normalizations). In-place safe: all g_w loads complete into
// registers before the first barrier; stores happen after the last.
// ---------------------------------------------------------------------------
__global__ __launch_bounds__(256) void wfwht2_kernel() {
    __shared__ float tp[4096 + 256];
    const int row = blockIdx.x;               // o-row
    const int tid = threadIdx.x;
    const int hi = tid >> 4, lo = tid & 15;
    __half* rowp = g_w + (size_t)row * NF;

    float v[16];
    const __half2* ip = (const __half2*)(rowp + tid * 16);
    #pragma unroll
    for (int q = 0; q < 8; q++) {
        float2 f = __half22float2(ip[q]);
        v[q*2+0] = f.x; v[q*2+1] = f.y;
    }

    // bits 0-3 (view1)
    #pragma unroll
    for (int h = 1; h < 16; h <<= 1)
        #pragma unroll
        for (int i = 0; i < 16; i++)
            if (!(i & h)) {
                float a = v[i], b = v[i ^ h];
                v[i] = a + b; v[i ^ h] = a - b;
            }

    // transpose 1: view1 -> view2
    #pragma unroll
    for (int j = 0; j < 16; j++) tp[tid * 17 + j] = v[j];
    __syncthreads();
    #pragma unroll
    for (int j = 0; j < 16; j++) v[j] = tp[hi * 272 + j * 17 + lo];

    // bits 4-7 (view2)
    #pragma unroll
    for (int h = 1; h < 16; h <<= 1)
        #pragma unroll
        for (int i = 0; i < 16; i++)
            if (!(i & h)) {
                float a = v[i], b = v[i ^ h];
                v[i] = a + b; v[i ^ h] = a - b;
            }

    // transpose 2: write-back to same per-thread addresses
    #pragma unroll
    for (int j = 0; j < 16; j++) tp[hi * 272 + j * 17 + lo] = v[j];
    __syncthreads();
    #pragma unroll
    for (int j = 0; j < 16; j++) v[j] = tp[j * 272 + tid + hi];

    // bits 8-11 (view3)
    #pragma unroll
    for (int h = 1; h < 16; h <<= 1)
        #pragma unroll
        for (int i = 0; i < 16; i++)
            if (!(i & h)) {
                float a = v[i], b = v[i ^ h];
                v[i] = a + b; v[i ^ h] = a - b;
            }

    #pragma unroll
    for (int j = 0; j < 16; j++)
        rowp[j * 256 + tid] = __float2half_rn(v[j] * 0.000244140625f); // /4096
}

// ---------------------------------------------------------------------------
// Kernel 3: fp16 mma.sync GEMM + fused epilogue.  R8 mainloop FROZEN
// (tensor=74% = sm_103a mma.sync dispatch ceiling, invariant R8/R9/R11).
// Epilogue: out = acc * SV + bias (1/4096 already folded into W'').
// ---------------------------------------------------------------------------
#define BM 256
#define BN 128
#define BKH 128                      // halves per k-stage (256 bytes, 2 sub-tiles)
#define KITERS (NF / BKH)            // 32
#define A_HALF_B (BM * 128)          // 32768
#define B_HALF_B (BN * 128)          // 16384
#define A_TILE_B (2 * A_HALF_B)      // 65536
#define B_TILE_B (2 * B_HALF_B)      // 32768
#define STAGE_B  (A_TILE_B + B_TILE_B)      // 98304
#define GEMM_SMEM (2 * STAGE_B)             // 196608

__device__ __forceinline__ uint32_t sw128(uint32_t o) { return o ^ ((o >> 3) & 0x70); }

__device__ __forceinline__ void cpa(uint32_t dst, const void* src) {
    asm volatile("cp.async.cg.shared.global [%0], [%1], 16;" :: "r"(dst), "l"(src));
}

__device__ __forceinline__ void ldsm4(uint32_t* r, uint32_t addr) {
    asm volatile("ldmatrix.sync.aligned.m8n8.x4.shared.b16 {%0,%1,%2,%3}, [%4];"
                 : "=r"(r[0]), "=r"(r[1]), "=r"(r[2]), "=r"(r[3]) : "r"(addr));
}

__device__ __forceinline__ void load_stage(uint32_t base, int st, int mBase,
                                           int nBase, int tid) {
    const int k0 = st * BKH;
    const __half* A = g_x + (size_t)mBase * NF + k0;
    const __half* B = g_w + (size_t)nBase * NF + k0;
    #pragma unroll
    for (int i = 0; i < 16; i++) {                // A: 4096 x 16B
        int id = tid + (i << 8);
        int r = id >> 4, c16 = id & 15;
        cpa(base + (c16 >> 3) * A_HALF_B + sw128(r * 128 + (c16 & 7) * 16),
            A + (size_t)r * NF + c16 * 8);
    }
    #pragma unroll
    for (int i = 0; i < 8; i++) {                 // B: 2048 x 16B
        int id = tid + (i << 8);
        int r = id >> 4, c16 = id & 15;
        cpa(base + A_TILE_B + (c16 >> 3) * B_HALF_B + sw128(r * 128 + (c16 & 7) * 16),
            B + (size_t)r * NF + c16 * 8);
    }
    asm volatile("cp.async.commit_group;");
}

__global__ __launch_bounds__(256, 1) void gemm_f16_kernel(
        const float* __restrict__ SV, const float* __restrict__ bias,
        float* __restrict__ out) {
    extern __shared__ __align__(1024) uint8_t sm[];
    const uint32_t smem_base = (uint32_t)__cvta_generic_to_shared(sm);

    const int tid  = threadIdx.x;
    const int warp = tid >> 5, lane = tid & 31;
    const int wm = warp >> 1, wn = warp & 1;       // 4 x 2 warp grid, 64x64 tiles
    const int g  = lane >> 2, t = lane & 3;
    const int mBase = blockIdx.y * BM;
    const int nBase = blockIdx.x * BN;

    // ldmatrix lane addressing
    const int a_row  = lane & 15;
    const int a_koff = (lane >> 4) * 16;           // 0/16 bytes
    const int b_row  = (lane & 7) + ((lane >> 4) & 1) * 8;
    const int b_koff = ((lane >> 3) & 1) * 16;

    uint32_t aBase[4], aXor[4], bBase[4], bXor[4];
    #pragma unroll
    for (int mt = 0; mt < 4; mt++) {
        uint32_t rb = (wm * 64 + mt * 16 + a_row) * 128;
        aBase[mt] = rb; aXor[mt] = (rb >> 3) & 0x70;
    }
    #pragma unroll
    for (int np = 0; np < 4; np++) {
        uint32_t rb = (wn * 64 + np * 16 + b_row) * 128;
        bBase[np] = rb; bXor[np] = (rb >> 3) & 0x70;
    }

    float acc[4][8][4];
    #pragma unroll
    for (int a = 0; a < 4; a++)
        #pragma unroll
        for (int b = 0; b < 8; b++)
            #pragma unroll
            for (int c = 0; c < 4; c++) acc[a][b][c] = 0.f;

    load_stage(smem_base, 0, mBase, nBase, tid);

    for (int s = 0; s < KITERS; s++) {
        asm volatile("cp.async.wait_group 0;" ::: "memory");
        __syncthreads();
        if (s + 1 < KITERS)
            load_stage(smem_base + ((s + 1) & 1) * STAGE_B, s + 1,
                       mBase, nBase, tid);

        const uint32_t As = smem_base + (s & 1) * STAGE_B;
        const uint32_t Bs = As + A_TILE_B;

        uint32_t af[2][4][4], bf[2][4][4];
        #pragma unroll
        for (int mt = 0; mt < 4; mt++)
            ldsm4(af[0][mt], As + aBase[mt] + (a_koff ^ aXor[mt]));
        #pragma unroll
        for (int np = 0; np < 4; np++)
            ldsm4(bf[0][np], Bs + bBase[np] + (b_koff ^ bXor[np]));

        #pragma unroll
        for (int kc = 0; kc < 8; kc++) {           // 8 k-chunks of 16
            const int cur = kc & 1, nxt = cur ^ 1;
            if (kc < 7) {
                const int kn = kc + 1;
                const uint32_t ah = As + (kn >> 2) * A_HALF_B;
                const uint32_t bh = Bs + (kn >> 2) * B_HALF_B;
                const uint32_t ak = (kn & 3) * 32 + a_koff;
                const uint32_t bk = (kn & 3) * 32 + b_koff;
                #pragma unroll
                for (int mt = 0; mt < 4; mt++)
                    ldsm4(af[nxt][mt], ah + aBase[mt] + (ak ^ aXor[mt]));
                #pragma unroll
                for (int np = 0; np < 4; np++)
                    ldsm4(bf[nxt][np], bh + bBase[np] + (bk ^ bXor[np]));
            }
            #pragma unroll
            for (int mt = 0; mt < 4; mt++)
                #pragma unroll
                for (int nt = 0; nt < 8; nt++) {
                    float* c = acc[mt][nt];
                    const uint32_t b0 = bf[cur][nt >> 1][(nt & 1) * 2 + 0];
                    const uint32_t b1 = bf[cur][nt >> 1][(nt & 1) * 2 + 1];
                    asm volatile(
                        "mma.sync.aligned.m16n8k16.row.col.f32.f16.f16.f32 "
                        "{%0,%1,%2,%3}, {%4,%5,%6,%7}, {%8,%9}, {%0,%1,%2,%3};"
                        : "+f"(c[0]), "+f"(c[1]), "+f"(c[2]), "+f"(c[3])
                        : "r"(af[cur][mt][0]), "r"(af[cur][mt][1]),
                          "r"(af[cur][mt][2]), "r"(af[cur][mt][3]),
                          "r"(b0), "r"(b1));
                }
        }
        // no bottom barrier: top barrier of next iter orders compute(s)
        // before the cp.async overwrite of buffer s&1 (issued at iter s+1).
    }

    // Fused epilogue: out = acc * SV + bias   (1/4096 folded into W'')
    #pragma unroll
    for (int nt = 0; nt < 8; nt++) {
        const int c0 = nBase + wn * 64 + nt * 8 + (t << 1);
        const float sv0 = __ldg(SV + c0);
        const float sv1 = __ldg(SV + c0 + 1);
        const float bb0 = __ldg(bias + c0);
        const float bb1 = __ldg(bias + c0 + 1);
        #pragma unroll
        for (int mt = 0; mt < 4; mt++) {
            const int r0 = mBase + wm * 64 + mt * 16 + g;
            float* c = acc[mt][nt];
            *(float2*)(out + (size_t)r0 * OF + c0) =
                make_float2(c[0] * sv0 + bb0, c[1] * sv1 + bb1);
            *(float2*)(out + (size_t)(r0 + 8) * OF + c0) =
                make_float2(c[2] * sv0 + bb0, c[3] * sv1 + bb1);
        }
    }
}

// ---------------------------------------------------------------------------
// Launch: serial (stream overlap measured neutral/regressive in R10/R13).
// ---------------------------------------------------------------------------
extern "C" void kernel_launch(void* const* d_in, const int* in_sizes, int n_in,
                              void* d_out, int out_size) {
    const float* input  = (const float*)d_in[0];
    const float* SU     = (const float*)d_in[1];
    const float* SV     = (const float*)d_in[2];
    const float* cb     = (const float*)d_in[3];
    const int*   Qidxs  = (const int*)d_in[4];
    const float* Wscale = (const float*)d_in[5];
    const float* bias   = (const float*)d_in[6];
    float* out = (float*)d_out;

    cudaFuncSetAttribute(gemm_f16_kernel,
                         cudaFuncAttributeMaxDynamicSharedMemorySize, GEMM_SMEM);

    scale_kernel<<<TKN, 256>>>(input, SU, Wscale);
    // W'' = H_o * W * H_i / 4096 (dequant fused into first o-pass)
    wfwht0_kernel<<<dim3(64, NF / 128), 128>>>(cb, Qidxs);
    wfwht1_kernel<<<dim3(64, NF / 128), 128>>>();
    wfwht2_kernel<<<OF, 256>>>();
    gemm_f16_kernel<<<dim3(OF / BN, TKN / BM), 256, GEMM_SMEM>>>(SV, bias, out);
}

// round 17
// speedup vs baseline: 1.0116x; 1.0116x over previous
#include <cuda_runtime.h>
#include <cuda_fp16.h>
#include <cstdint>

#define TKN 8192   // tokens = 4*2048
#define NF  4096   // in features
#define OF  4096   // out features

// Scratch (static device globals -- allocation-free per harness rules)
__device__ __half g_x[(size_t)TKN * NF];    // 64 MB: fwht(input*SU)*scale, fp16
__device__ __half g_w[(size_t)OF * NF];     // 32 MB: W' = H*W, fp16
__device__ __half g_tmp[(size_t)OF * NF];   // 32 MB: W-FWHT intermediate

// ---------------------------------------------------------------------------
// Kernel 1: g_x = fp16( fwht(input * SU) * Wscale/64 )
// Shuffle-free FWHT: 3 register views x 4 bits, two padded-smem transposes
// (R14-verified best form).
// ---------------------------------------------------------------------------
__global__ __launch_bounds__(256) void fwht_in_kernel(
        const float* __restrict__ in, const float* __restrict__ SU,
        const float* __restrict__ wscale) {
    __shared__ float s[4096 + 256];
    const int row = blockIdx.x;
    const int tid = threadIdx.x;
    const int hi = tid >> 4, lo = tid & 15;

    float v[16];
    const float4* ip = (const float4*)(in + (size_t)row * NF + tid * 16);
    const float4* up = (const float4*)(SU + tid * 16);
    #pragma unroll
    for (int q = 0; q < 4; q++) {
        float4 a = ip[q], b = up[q];
        v[q*4+0] = a.x*b.x; v[q*4+1] = a.y*b.y;
        v[q*4+2] = a.z*b.z; v[q*4+3] = a.w*b.w;
    }

    // bits 0-3 (view1: i = tid*16 + j)
    #pragma unroll
    for (int h = 1; h < 16; h <<= 1)
        #pragma unroll
        for (int i = 0; i < 16; i++)
            if (!(i & h)) {
                float a = v[i], b = v[i ^ h];
                v[i] = a + b; v[i ^ h] = a - b;
            }

    // transpose 1: view1 -> view2 (i = hi*256 + j*16 + lo)
    #pragma unroll
    for (int r = 0; r < 16; r++) s[tid * 17 + r] = v[r];
    __syncthreads();
    #pragma unroll
    for (int r = 0; r < 16; r++) v[r] = s[hi * 272 + r * 17 + lo];

    // bits 4-7
    #pragma unroll
    for (int h = 1; h < 16; h <<= 1)
        #pragma unroll
        for (int i = 0; i < 16; i++)
            if (!(i & h)) {
                float a = v[i], b = v[i ^ h];
                v[i] = a + b; v[i ^ h] = a - b;
            }

    // transpose 2: write-back to same per-thread addresses (no barrier needed)
    #pragma unroll
    for (int r = 0; r < 16; r++) s[hi * 272 + r * 17 + lo] = v[r];
    __syncthreads();
    #pragma unroll
    for (int r = 0; r < 16; r++) v[r] = s[r * 272 + tid + hi];

    // bits 8-11 (view3: i = j*256 + tid)
    #pragma unroll
    for (int h = 1; h < 16; h <<= 1)
        #pragma unroll
        for (int i = 0; i < 16; i++)
            if (!(i & h)) {
                float a = v[i], b = v[i ^ h];
                v[i] = a + b; v[i ^ h] = a - b;
            }

    const float sc = wscale[0] * 0.015625f;   // Wscale / sqrt(4096)
    __half* dst = g_x + (size_t)row * NF + tid;
    #pragma unroll
    for (int r = 0; r < 16; r++)
        dst[r * 256] = __float2half_rn(v[r] * sc);
}

// ---------------------------------------------------------------------------
// Kernel 2: fused dequant + FWHT pass 0 over output-dim bits 0..5.
// 128 threads/block, ONE half-lane per thread. NEW: the block's 64x32 Qidxs
// tile (8KB) is staged through smem with coalesced 128B loads, removing the
// 4x-redundant scalar L2 gather (each code was fetched by 4 threads).
// ---------------------------------------------------------------------------
__global__ __launch_bounds__(128) void wfwht0_kernel(
        const float* __restrict__ cb, const int* __restrict__ qidx) {
    __shared__ float scb[1024];               // cb: 256 codes x 4 floats = 4KB
    __shared__ int   sq[64 * 32];             // 64 o-rows x 32 qcols = 8KB
    const int tid = threadIdx.x;
    ((float4*)scb)[tid]       = ((const float4*)cb)[tid];
    ((float4*)scb)[tid + 128] = ((const float4*)cb)[tid + 128];

    const int b  = blockIdx.x;                // 0..63
    const int qc0 = blockIdx.y * 32;          // first qcol of this block
    // Stage Qidxs tile: rows b*64..b*64+63, qcols qc0..qc0+31 (coalesced)
    const int* qbase = qidx + (size_t)b * 64 * (NF / 4) + qc0;
    #pragma unroll
    for (int k = 0; k < 16; k++) {
        int idx = tid + (k << 7);             // 0..2047
        int r = idx >> 5, q = idx & 31;
        sq[idx] = __ldg(qbase + (size_t)r * (NF / 4) + q);
    }
    __syncthreads();

    const int hc = blockIdx.y * 128 + tid;    // half-col (= input index i)
    const int ql = tid >> 2;                  // local qcol (0..31)
    const int sub = hc & 3;                   // element within code

    float v[64];
    #pragma unroll
    for (int r = 0; r < 64; r++)
        v[r] = scb[sq[r * 32 + ql] * 4 + sub];

    #pragma unroll
    for (int h = 1; h < 64; h <<= 1)
        #pragma unroll
        for (int i = 0; i < 64; i++)
            if (!(i & h)) {
                float a = v[i], c = v[i ^ h];
                v[i] = a + c; v[i ^ h] = a - c;
            }

    __half* d = g_tmp + (size_t)b * 64 * NF + hc;
    #pragma unroll
    for (int r = 0; r < 64; r++)
        d[(size_t)r * NF] = __float2half_rn(v[r]);
}

// ---------------------------------------------------------------------------
// Kernel 2b: FWHT pass 1 over output-dim bits 6..11 (rows o = b + 64*r).
// ---------------------------------------------------------------------------
__global__ __launch_bounds__(128) void wfwht1_kernel() {
    const int b  = blockIdx.x;                // 0..63
    const int hc = blockIdx.y * 128 + threadIdx.x;
    const __half* s = g_tmp + (size_t)b * NF + hc;
    __half*       d = g_w   + (size_t)b * NF + hc;
    const size_t rstep = (size_t)64 * NF;

    float v[64];
    #pragma unroll
    for (int r = 0; r < 64; r++)
        v[r] = __half2float(__ldg(s + r * rstep));

    #pragma unroll
    for (int h = 1; h < 64; h <<= 1)
        #pragma unroll
        for (int i = 0; i < 64; i++)
            if (!(i & h)) {
                float a = v[i], c = v[i ^ h];
                v[i] = a + c; v[i ^ h] = a - c;
            }

    #pragma unroll
    for (int r = 0; r < 64; r++)
        d[r * rstep] = __float2half_rn(v[r]);
}

// ---------------------------------------------------------------------------
// Kernel 3: fp16 mma.sync GEMM + fused epilogue.  R8 configuration, FROZEN
// (tensor=74% is the sm_103a mma.sync dispatch ceiling, invariant across
// R8/R9/R11 schedule variants — do not touch).
// ---------------------------------------------------------------------------
#define BM 256
#define BN 128
#define BKH 128                      // halves per k-stage (256 bytes, 2 sub-tiles)
#define KITERS (NF / BKH)            // 32
#define A_HALF_B (BM * 128)          // 32768
#define B_HALF_B (BN * 128)          // 16384
#define A_TILE_B (2 * A_HALF_B)      // 65536
#define B_TILE_B (2 * B_HALF_B)      // 32768
#define STAGE_B  (A_TILE_B + B_TILE_B)      // 98304
#define GEMM_SMEM (2 * STAGE_B)             // 196608

__device__ __forceinline__ uint32_t sw128(uint32_t o) { return o ^ ((o >> 3) & 0x70); }

__device__ __forceinline__ void cpa(uint32_t dst, const void* src) {
    asm volatile("cp.async.cg.shared.global [%0], [%1], 16;" :: "r"(dst), "l"(src));
}

__device__ __forceinline__ void ldsm4(uint32_t* r, uint32_t addr) {
    asm volatile("ldmatrix.sync.aligned.m8n8.x4.shared.b16 {%0,%1,%2,%3}, [%4];"
                 : "=r"(r[0]), "=r"(r[1]), "=r"(r[2]), "=r"(r[3]) : "r"(addr));
}

__device__ __forceinline__ void load_stage(uint32_t base, int st, int mBase,
                                           int nBase, int tid) {
    const int k0 = st * BKH;
    const __half* A = g_x + (size_t)mBase * NF + k0;
    const __half* B = g_w + (size_t)nBase * NF + k0;
    #pragma unroll
    for (int i = 0; i < 16; i++) {                // A: 4096 x 16B
        int id = tid + (i << 8);
        int r = id >> 4, c16 = id & 15;
        cpa(base + (c16 >> 3) * A_HALF_B + sw128(r * 128 + (c16 & 7) * 16),
            A + (size_t)r * NF + c16 * 8);
    }
    #pragma unroll
    for (int i = 0; i < 8; i++) {                 // B: 2048 x 16B
        int id = tid + (i << 8);
        int r = id >> 4, c16 = id & 15;
        cpa(base + A_TILE_B + (c16 >> 3) * B_HALF_B + sw128(r * 128 + (c16 & 7) * 16),
            B + (size_t)r * NF + c16 * 8);
    }
    asm volatile("cp.async.commit_group;");
}

__global__ __launch_bounds__(256, 1) void gemm_f16_kernel(
        const float* __restrict__ SV, const float* __restrict__ bias,
        float* __restrict__ out) {
    extern __shared__ __align__(1024) uint8_t sm[];
    const uint32_t smem_base = (uint32_t)__cvta_generic_to_shared(sm);

    const int tid  = threadIdx.x;
    const int warp = tid >> 5, lane = tid & 31;
    const int wm = warp >> 1, wn = warp & 1;       // 4 x 2 warp grid, 64x64 tiles
    const int g  = lane >> 2, t = lane & 3;
    const int mBase = blockIdx.y * BM;
    const int nBase = blockIdx.x * BN;

    // ldmatrix lane addressing
    const int a_row  = lane & 15;
    const int a_koff = (lane >> 4) * 16;           // 0/16 bytes
    const int b_row  = (lane & 7) + ((lane >> 4) & 1) * 8;
    const int b_koff = ((lane >> 3) & 1) * 16;

    uint32_t aBase[4], aXor[4], bBase[4], bXor[4];
    #pragma unroll
    for (int mt = 0; mt < 4; mt++) {
        uint32_t rb = (wm * 64 + mt * 16 + a_row) * 128;
        aBase[mt] = rb; aXor[mt] = (rb >> 3) & 0x70;
    }
    #pragma unroll
    for (int np = 0; np < 4; np++) {
        uint32_t rb = (wn * 64 + np * 16 + b_row) * 128;
        bBase[np] = rb; bXor[np] = (rb >> 3) & 0x70;
    }

    float acc[4][8][4];
    #pragma unroll
    for (int a = 0; a < 4; a++)
        #pragma unroll
        for (int b = 0; b < 8; b++)
            #pragma unroll
            for (int c = 0; c < 4; c++) acc[a][b][c] = 0.f;

    load_stage(smem_base, 0, mBase, nBase, tid);

    for (int s = 0; s < KITERS; s++) {
        asm volatile("cp.async.wait_group 0;" ::: "memory");
        __syncthreads();
        if (s + 1 < KITERS)
            load_stage(smem_base + ((s + 1) & 1) * STAGE_B, s + 1,
                       mBase, nBase, tid);

        const uint32_t As = smem_base + (s & 1) * STAGE_B;
        const uint32_t Bs = As + A_TILE_B;

        uint32_t af[2][4][4], bf[2][4][4];
        #pragma unroll
        for (int mt = 0; mt < 4; mt++)
            ldsm4(af[0][mt], As + aBase[mt] + (a_koff ^ aXor[mt]));
        #pragma unroll
        for (int np = 0; np < 4; np++)
            ldsm4(bf[0][np], Bs + bBase[np] + (b_koff ^ bXor[np]));

        #pragma unroll
        for (int kc = 0; kc < 8; kc++) {           // 8 k-chunks of 16
            const int cur = kc & 1, nxt = cur ^ 1;
            if (kc < 7) {
                const int kn = kc + 1;
                const uint32_t ah = As + (kn >> 2) * A_HALF_B;
                const uint32_t bh = Bs + (kn >> 2) * B_HALF_B;
                const uint32_t ak = (kn & 3) * 32 + a_koff;
                const uint32_t bk = (kn & 3) * 32 + b_koff;
                #pragma unroll
                for (int mt = 0; mt < 4; mt++)
                    ldsm4(af[nxt][mt], ah + aBase[mt] + (ak ^ aXor[mt]));
                #pragma unroll
                for (int np = 0; np < 4; np++)
                    ldsm4(bf[nxt][np], bh + bBase[np] + (bk ^ bXor[np]));
            }
            #pragma unroll
            for (int mt = 0; mt < 4; mt++)
                #pragma unroll
                for (int nt = 0; nt < 8; nt++) {
                    float* c = acc[mt][nt];
                    const uint32_t b0 = bf[cur][nt >> 1][(nt & 1) * 2 + 0];
                    const uint32_t b1 = bf[cur][nt >> 1][(nt & 1) * 2 + 1];
                    asm volatile(
                        "mma.sync.aligned.m16n8k16.row.col.f32.f16.f16.f32 "
                        "{%0,%1,%2,%3}, {%4,%5,%6,%7}, {%8,%9}, {%0,%1,%2,%3};"
                        : "+f"(c[0]), "+f"(c[1]), "+f"(c[2]), "+f"(c[3])
                        : "r"(af[cur][mt][0]), "r"(af[cur][mt][1]),
                          "r"(af[cur][mt][2]), "r"(af[cur][mt][3]),
                          "r"(b0), "r"(b1));
                }
        }
        // no bottom barrier: top barrier of next iter orders compute(s)
        // before the cp.async overwrite of buffer s&1 (issued at iter s+1).
    }

    // Fused epilogue: out = acc/64 * SV + bias
    const float isq = 0.015625f;   // 1/sqrt(4096)
    #pragma unroll
    for (int nt = 0; nt < 8; nt++) {
        const int c0 = nBase + wn * 64 + nt * 8 + (t << 1);
        const float sv0 = __ldg(SV + c0)     * isq;
        const float sv1 = __ldg(SV + c0 + 1) * isq;
        const float bb0 = __ldg(bias + c0);
        const float bb1 = __ldg(bias + c0 + 1);
        #pragma unroll
        for (int mt = 0; mt < 4; mt++) {
            const int r0 = mBase + wm * 64 + mt * 16 + g;
            float* c = acc[mt][nt];
            *(float2*)(out + (size_t)r0 * OF + c0) =
                make_float2(c[0] * sv0 + bb0, c[1] * sv1 + bb1);
            *(float2*)(out + (size_t)(r0 + 8) * OF + c0) =
                make_float2(c[2] * sv0 + bb0, c[3] * sv1 + bb1);
        }
    }
}

// ---------------------------------------------------------------------------
// Launch: serial (stream overlap measured neutral/regressive in R10/R13).
// ---------------------------------------------------------------------------
extern "C" void kernel_launch(void* const* d_in, const int* in_sizes, int n_in,
                              void* d_out, int out_size) {
    const float* input  = (const float*)d_in[0];
    const float* SU     = (const float*)d_in[1];
    const float* SV     = (const float*)d_in[2];
    const float* cb     = (const float*)d_in[3];
    const int*   Qidxs  = (const int*)d_in[4];
    const float* Wscale = (const float*)d_in[5];
    const float* bias   = (const float*)d_in[6];
    float* out = (float*)d_out;

    cudaFuncSetAttribute(gemm_f16_kernel,
                         cudaFuncAttributeMaxDynamicSharedMemorySize, GEMM_SMEM);

    fwht_in_kernel<<<TKN, 256>>>(input, SU, Wscale);
    // W' = H * W  (FWHT along output dim; pass 0 fused with codebook dequant)
    wfwht0_kernel<<<dim3(64, NF / 128), 128>>>(cb, Qidxs);
    wfwht1_kernel<<<dim3(64, NF / 128), 128>>>();
    gemm_f16_kernel<<<dim3(OF / BN, TKN / BM), 256, GEMM_SMEM>>>(SV, bias, out);
}